// round 1
// baseline (speedup 1.0000x reference)
#include <cuda_runtime.h>

#define SEQ 2048
#define BATCH 1024
#define NL 6
#define ACT_MASK 0x00FFFFFFu

__device__ __forceinline__ float fexp2e(float x) {
    // exp(x) via ex2.approx (rel err ~2^-22)
    float y;
    asm("ex2.approx.ftz.f32 %0, %1;" : "=f"(y) : "f"(x * 1.4426950408889634f));
    return y;
}
__device__ __forceinline__ float frcp(float x) {
    float y;
    asm("rcp.approx.ftz.f32 %0, %1;" : "=f"(y) : "f"(x));
    return y;
}
__device__ __forceinline__ float sigm(float x) {
    return frcp(1.0f + fexp2e(-x));
}
__device__ __forceinline__ float tanh_(float x) {
    // tanh(x) = 2/(1+exp(-2x)) - 1
    return fmaf(2.0f, frcp(1.0f + fexp2e(-2.0f * x)), -1.0f);
}

// One warp per batch element. Lane = l*4 + j  (l = layer 0..5, j = h-element 0..3).
// Lanes 24..31 idle. Layers run as a wavefront pipeline: at tick k, layer l
// processes timestep t = k - l. h values cross layers via warp shuffles.
__global__ __launch_bounds__(256) void lstm_reg_kernel(
    const float* __restrict__ x,      // [S, B, 4]
    const float* __restrict__ w_ih,   // [6, 16, 4]
    const float* __restrict__ w_hh,   // [6, 16, 4]
    const float* __restrict__ b_ih,   // [6, 16]
    const float* __restrict__ b_hh,   // [6, 16]
    const float* __restrict__ reg_w,  // [1, 4]
    const float* __restrict__ reg_b,  // [1]
    float* __restrict__ out)          // [S, B, 1]
{
    const int lane = threadIdx.x & 31;
    const int warp = threadIdx.x >> 5;
    if (lane >= 24) return;

    const int b = blockIdx.x * 8 + warp;     // batch element
    const int l = lane >> 2;                 // layer
    const int j = lane & 3;                  // h element

    // Per-lane weights in registers: 4 gate rows (i, f, g, o for element j).
    float wih[4][4], whh[4][4], bias[4];
#pragma unroll
    for (int g = 0; g < 4; ++g) {
        const int row = l * 16 + g * 4 + j;  // gate order: i(0-3) f(4-7) g(8-11) o(12-15)
#pragma unroll
        for (int i = 0; i < 4; ++i) {
            wih[g][i] = w_ih[row * 4 + i];
            whh[g][i] = w_hh[row * 4 + i];
        }
        bias[g] = b_ih[row] + b_hh[row];
    }
    const float rw0 = reg_w[0], rw1 = reg_w[1], rw2 = reg_w[2], rw3 = reg_w[3];
    const float rb = reg_b[0];

    const float4* __restrict__ x4 = (const float4*)x;

    float h = 0.0f, c = 0.0f;
    const int base_in = (l == 0) ? 0 : (l - 1) * 4;  // producer lanes (layer l-1)
    const int base_h  = l * 4;                       // own-layer lanes

#pragma unroll 1
    for (int k = 0; k < SEQ + NL; ++k) {
        // Own-layer previous h (THE critical path) — issue first.
        float hv0 = __shfl_sync(ACT_MASK, h, base_h + 0);
        float hv1 = __shfl_sync(ACT_MASK, h, base_h + 1);
        float hv2 = __shfl_sync(ACT_MASK, h, base_h + 2);
        float hv3 = __shfl_sync(ACT_MASK, h, base_h + 3);
        // Input vector = layer (l-1)'s h from the previous tick (timestep k-l).
        float iv0 = __shfl_sync(ACT_MASK, h, base_in + 0);
        float iv1 = __shfl_sync(ACT_MASK, h, base_in + 1);
        float iv2 = __shfl_sync(ACT_MASK, h, base_in + 2);
        float iv3 = __shfl_sync(ACT_MASK, h, base_in + 3);

        if (l == 0 && k < SEQ) {
            const float4 xv = x4[(size_t)k * BATCH + b];
            iv0 = xv.x; iv1 = xv.y; iv2 = xv.z; iv3 = xv.w;
        }

        // Linear head: hv* on layer-5 lanes = h5 at timestep k-6 (prev tick's h).
        if (lane == 20) {
            const int t_out = k - NL;
            if (t_out >= 0) {
                float y = rb;
                y = fmaf(rw0, hv0, y);
                y = fmaf(rw1, hv1, y);
                y = fmaf(rw2, hv2, y);
                y = fmaf(rw3, hv3, y);
                out[(size_t)t_out * BATCH + b] = y;
            }
        }

        const int t = k - l;
        if ((unsigned)t < SEQ) {
            // Two independent 4-FMA chains per gate (input-proj and recurrent),
            // 4 gates in parallel -> short critical path.
            float a0 = bias[0], a1 = bias[1], a2 = bias[2], a3 = bias[3];
            float p0 = 0.f, p1 = 0.f, p2 = 0.f, p3 = 0.f;

            a0 = fmaf(wih[0][0], iv0, a0); p0 = fmaf(whh[0][0], hv0, p0);
            a1 = fmaf(wih[1][0], iv0, a1); p1 = fmaf(whh[1][0], hv0, p1);
            a2 = fmaf(wih[2][0], iv0, a2); p2 = fmaf(whh[2][0], hv0, p2);
            a3 = fmaf(wih[3][0], iv0, a3); p3 = fmaf(whh[3][0], hv0, p3);

            a0 = fmaf(wih[0][1], iv1, a0); p0 = fmaf(whh[0][1], hv1, p0);
            a1 = fmaf(wih[1][1], iv1, a1); p1 = fmaf(whh[1][1], hv1, p1);
            a2 = fmaf(wih[2][1], iv1, a2); p2 = fmaf(whh[2][1], hv1, p2);
            a3 = fmaf(wih[3][1], iv1, a3); p3 = fmaf(whh[3][1], hv1, p3);

            a0 = fmaf(wih[0][2], iv2, a0); p0 = fmaf(whh[0][2], hv2, p0);
            a1 = fmaf(wih[1][2], iv2, a1); p1 = fmaf(whh[1][2], hv2, p1);
            a2 = fmaf(wih[2][2], iv2, a2); p2 = fmaf(whh[2][2], hv2, p2);
            a3 = fmaf(wih[3][2], iv2, a3); p3 = fmaf(whh[3][2], hv2, p3);

            a0 = fmaf(wih[0][3], iv3, a0); p0 = fmaf(whh[0][3], hv3, p0);
            a1 = fmaf(wih[1][3], iv3, a1); p1 = fmaf(whh[1][3], hv3, p1);
            a2 = fmaf(wih[2][3], iv3, a2); p2 = fmaf(whh[2][3], hv3, p2);
            a3 = fmaf(wih[3][3], iv3, a3); p3 = fmaf(whh[3][3], hv3, p3);

            const float gi = a0 + p0;   // input gate preact
            const float gf = a1 + p1;   // forget gate
            const float gg = a2 + p2;   // cell candidate
            const float go = a3 + p3;   // output gate

            const float ig = sigm(gi);
            const float fg = sigm(gf);
            const float og = sigm(go);
            const float cc = tanh_(gg);

            c = fmaf(fg, c, ig * cc);
            h = og * tanh_(c);
        }
    }
}

extern "C" void kernel_launch(void* const* d_in, const int* in_sizes, int n_in,
                              void* d_out, int out_size) {
    const float* x     = (const float*)d_in[0];
    const float* w_ih  = (const float*)d_in[1];
    const float* w_hh  = (const float*)d_in[2];
    const float* b_ih  = (const float*)d_in[3];
    const float* b_hh  = (const float*)d_in[4];
    const float* reg_w = (const float*)d_in[5];
    const float* reg_b = (const float*)d_in[6];
    float* out = (float*)d_out;

    // 1024 batch elements, one warp each; 8 warps per block -> 128 blocks
    lstm_reg_kernel<<<128, 256>>>(x, w_ih, w_hh, b_ih, b_hh, reg_w, reg_b, out);
}

// round 2
// speedup vs baseline: 2.3823x; 2.3823x over previous
#include <cuda_runtime.h>

#define SEQ 2048
#define BATCH 1024
#define NL 6
#define UF 8
#define MASK 0x0FFFFFFFu   // lanes 0..27 active

__device__ __forceinline__ float tanh_ap(float x) {
    float y;
    asm("tanh.approx.f32 %0, %1;" : "=f"(y) : "f"(x));
    return y;
}
__device__ __forceinline__ float sigm_ap(float x) {
    return fmaf(0.5f, tanh_ap(0.5f * x), 0.5f);
}

struct LaneState {
    float wih[4][4], whh[4][4], bias[4];
    float h, c;
    float rw0, rw1, rw2, rw3, rb;
    int lane, l, bh, bi, b;
};

// One pipeline tick. Guarded=true adds fill/drain predicates.
// xptr: address of x element to prefetch into xslot (consumed UF ticks later).
template<bool Guarded>
__device__ __forceinline__ void tick(int k, LaneState& s, float& xslot,
                                     const float* __restrict__ xptr,
                                     float* __restrict__ out)
{
    // h from end of previous tick crosses lanes.
    const float hv0 = __shfl_sync(MASK, s.h, s.bh + 0);
    const float hv1 = __shfl_sync(MASK, s.h, s.bh + 1);
    const float hv2 = __shfl_sync(MASK, s.h, s.bh + 2);
    const float hv3 = __shfl_sync(MASK, s.h, s.bh + 3);
    const float iv0 = __shfl_sync(MASK, s.h, s.bi + 0);
    const float iv1 = __shfl_sync(MASK, s.h, s.bi + 1);
    const float iv2 = __shfl_sync(MASK, s.h, s.bi + 2);
    const float iv3 = __shfl_sync(MASK, s.h, s.bi + 3);

    // Linear head: on lane 20, hv* = layer-5 h at timestep k-6.
    float y = s.rb;
    y = fmaf(s.rw0, hv0, y);
    y = fmaf(s.rw1, hv1, y);
    y = fmaf(s.rw2, hv2, y);
    y = fmaf(s.rw3, hv3, y);
    const int t_out = k - NL;
    if (s.lane == 20 && (!Guarded || (unsigned)t_out < SEQ))
        out[(size_t)t_out * BATCH + s.b] = y;

    // Gate pre-activations: two independent 4-FMA chains per gate.
    float a0 = s.bias[0], a1 = s.bias[1], a2 = s.bias[2], a3 = s.bias[3];
    float p0, p1, p2, p3;
    a0 = fmaf(s.wih[0][0], iv0, a0); p0 = s.whh[0][0] * hv0;
    a1 = fmaf(s.wih[1][0], iv0, a1); p1 = s.whh[1][0] * hv0;
    a2 = fmaf(s.wih[2][0], iv0, a2); p2 = s.whh[2][0] * hv0;
    a3 = fmaf(s.wih[3][0], iv0, a3); p3 = s.whh[3][0] * hv0;

    a0 = fmaf(s.wih[0][1], iv1, a0); p0 = fmaf(s.whh[0][1], hv1, p0);
    a1 = fmaf(s.wih[1][1], iv1, a1); p1 = fmaf(s.whh[1][1], hv1, p1);
    a2 = fmaf(s.wih[2][1], iv1, a2); p2 = fmaf(s.whh[2][1], hv1, p2);
    a3 = fmaf(s.wih[3][1], iv1, a3); p3 = fmaf(s.whh[3][1], hv1, p3);

    a0 = fmaf(s.wih[0][2], iv2, a0); p0 = fmaf(s.whh[0][2], hv2, p0);
    a1 = fmaf(s.wih[1][2], iv2, a1); p1 = fmaf(s.whh[1][2], hv2, p1);
    a2 = fmaf(s.wih[2][2], iv2, a2); p2 = fmaf(s.whh[2][2], hv2, p2);
    a3 = fmaf(s.wih[3][2], iv2, a3); p3 = fmaf(s.whh[3][2], hv2, p3);

    a0 = fmaf(s.wih[0][3], iv3, a0); p0 = fmaf(s.whh[0][3], hv3, p0);
    a1 = fmaf(s.wih[1][3], iv3, a1); p1 = fmaf(s.whh[1][3], hv3, p1);
    a2 = fmaf(s.wih[2][3], iv3, a2); p2 = fmaf(s.whh[2][3], hv3, p2);
    a3 = fmaf(s.wih[3][3], iv3, a3); p3 = fmaf(s.whh[3][3], hv3, p3);

    const float gi = a0 + p0;
    const float gf = a1 + p1;
    const float gg = a2 + p2;
    const float go = a3 + p3;

    const float ig = sigm_ap(gi);
    const float fg = sigm_ap(gf);
    const float og = sigm_ap(go);
    const float cc = tanh_ap(gg);

    const float nc = fmaf(fg, s.c, ig * cc);
    const float nh = og * tanh_ap(nc);

    // Consume prefetched x, refill slot for tick k+UF.
    const float xv = xslot;
    xslot = *xptr;

    if (s.l == 6) {
        s.h = xv;                         // feeder lanes: h <- x[k+1]
    } else if (!Guarded || (unsigned)(k - s.l) < SEQ) {
        s.h = nh;
        s.c = nc;
    }
}

__global__ __launch_bounds__(256) void lstm_reg_kernel(
    const float* __restrict__ x,      // [S, B, 4]
    const float* __restrict__ w_ih,   // [6, 16, 4]
    const float* __restrict__ w_hh,   // [6, 16, 4]
    const float* __restrict__ b_ih,   // [6, 16]
    const float* __restrict__ b_hh,   // [6, 16]
    const float* __restrict__ reg_w,  // [1, 4]
    const float* __restrict__ reg_b,  // [1]
    float* __restrict__ out)          // [S, B, 1]
{
    const int lane = threadIdx.x & 31;
    const int warp = threadIdx.x >> 5;
    if (lane >= 28) return;

    LaneState s;
    s.lane = lane;
    s.b = blockIdx.x * 8 + warp;
    s.l = lane >> 2;                     // 0..5 = LSTM layers, 6 = x feeder
    const int j = lane & 3;
    s.bh = s.l * 4;                      // own-group lanes (feeder: 24)
    s.bi = (s.l == 0) ? 24 : (s.l - 1) * 4;

#pragma unroll
    for (int g = 0; g < 4; ++g) {
#pragma unroll
        for (int i = 0; i < 4; ++i) { s.wih[g][i] = 0.f; s.whh[g][i] = 0.f; }
        s.bias[g] = 0.f;
    }
    if (s.l < 6) {
#pragma unroll
        for (int g = 0; g < 4; ++g) {
            const int row = s.l * 16 + g * 4 + j;  // gate order i,f,g,o
#pragma unroll
            for (int i = 0; i < 4; ++i) {
                s.wih[g][i] = w_ih[row * 4 + i];
                s.whh[g][i] = w_hh[row * 4 + i];
            }
            s.bias[g] = b_ih[row] + b_hh[row];
        }
    }
    s.rw0 = reg_w[0]; s.rw1 = reg_w[1]; s.rw2 = reg_w[2]; s.rw3 = reg_w[3];
    s.rb  = reg_b[0];

    s.h = 0.f; s.c = 0.f;
    const float* xq = x + (size_t)s.b * 4 + j;   // per-lane column of x[t]
    if (s.l == 6) s.h = xq[0];                   // feeder starts with x[0]

    // Prefetch ring: slot u holds x[(tick)+1] for tick ≡ u (mod UF).
    float xbuf[UF];
#pragma unroll
    for (int u = 0; u < UF; ++u) {
        const int idx = (u + 1 < SEQ) ? (u + 1) : (SEQ - 1);
        xbuf[u] = xq[(size_t)idx * BATCH * 4];
    }

    // ---- fill chunk: ticks 0..7 (guarded) ----
#pragma unroll
    for (int u = 0; u < UF; ++u) {
        const int k = u;
        const int pidx = (k + 1 + UF < SEQ) ? (k + 1 + UF) : (SEQ - 1);
        tick<true>(k, s, xbuf[u], xq + (size_t)pidx * BATCH * 4, out);
    }

    // ---- main: ticks 8..2031, guard-free, linear prefetch ----
#pragma unroll 1
    for (int kc = UF; kc < 2032; kc += UF) {
        const float* xb = xq + (size_t)(kc + 1 + UF) * BATCH * 4;
#pragma unroll
        for (int u = 0; u < UF; ++u)
            tick<false>(kc + u, s, xbuf[u], xb + (size_t)u * BATCH * 4, out);
    }

    // ---- drain: ticks 2032..2055 (guarded) ----
#pragma unroll 1
    for (int kc = 2032; kc < 2032 + 3 * UF; kc += UF) {
#pragma unroll
        for (int u = 0; u < UF; ++u) {
            const int k = kc + u;
            const int pidx = (k + 1 + UF < SEQ) ? (k + 1 + UF) : (SEQ - 1);
            tick<true>(k, s, xbuf[u], xq + (size_t)pidx * BATCH * 4, out);
        }
    }
}

extern "C" void kernel_launch(void* const* d_in, const int* in_sizes, int n_in,
                              void* d_out, int out_size) {
    const float* x     = (const float*)d_in[0];
    const float* w_ih  = (const float*)d_in[1];
    const float* w_hh  = (const float*)d_in[2];
    const float* b_ih  = (const float*)d_in[3];
    const float* b_hh  = (const float*)d_in[4];
    const float* reg_w = (const float*)d_in[5];
    const float* reg_b = (const float*)d_in[6];
    float* out = (float*)d_out;

    lstm_reg_kernel<<<128, 256>>>(x, w_ih, w_hh, b_ih, b_hh, reg_w, reg_b, out);
}

// round 3
// speedup vs baseline: 2.5985x; 1.0907x over previous
#include <cuda_runtime.h>

#define SEQ 2048
#define BATCH 1024
#define NL 6
#define UF 8
#define MASK 0x0FFFFFFFu   // lanes 0..27 active

__device__ __forceinline__ float tanh_ap(float x) {
    float y;
    asm("tanh.approx.f32 %0, %1;" : "=f"(y) : "f"(x));
    return y;
}

// Predicated global store: no BSSY/BSYNC reconvergence.
__device__ __forceinline__ void store_pred(int flag, float* p, float v) {
    asm volatile(
        "{\n\t.reg .pred %%pp;\n\t"
        "setp.ne.s32 %%pp, %0, 0;\n\t"
        "@%%pp st.global.f32 [%1], %2;\n\t}"
        :: "r"(flag), "l"(p), "f"(v) : "memory");
}

struct LaneState {
    float wih[4][4], whh[4][4], bias[4];
    float h, c;                 // h holds 2*h_true (feeder lanes: x value)
    float rw0, rw1, rw2, rw3, rb;
    int lane, l, bh, bi, b;
    int isfeed;
};

// One pipeline tick, branch-free. Guarded adds fill/drain freezing via SELs.
template<bool Guarded>
__device__ __forceinline__ void tick(int k, LaneState& s, float& xslot,
                                     const float* __restrict__ xptr,
                                     float* __restrict__ out)
{
    // Cross-lane h from end of previous tick (values are 2*h; weights pre-halved).
    const float hv0 = __shfl_sync(MASK, s.h, s.bh + 0);
    const float hv1 = __shfl_sync(MASK, s.h, s.bh + 1);
    const float hv2 = __shfl_sync(MASK, s.h, s.bh + 2);
    const float hv3 = __shfl_sync(MASK, s.h, s.bh + 3);
    const float iv0 = __shfl_sync(MASK, s.h, s.bi + 0);
    const float iv1 = __shfl_sync(MASK, s.h, s.bi + 1);
    const float iv2 = __shfl_sync(MASK, s.h, s.bi + 2);
    const float iv3 = __shfl_sync(MASK, s.h, s.bi + 3);

    // Linear head (rw pre-scaled by 0.5 since hv = 2h). Predicated store.
    float y = s.rb;
    y = fmaf(s.rw0, hv0, y);
    y = fmaf(s.rw1, hv1, y);
    y = fmaf(s.rw2, hv2, y);
    y = fmaf(s.rw3, hv3, y);
    const int t_out = k - NL;
    const int t_ok = Guarded ? ((unsigned)t_out < SEQ) : 1;
    const int t_clamped = Guarded ? (t_out < 0 ? 0 : (t_out >= SEQ ? SEQ - 1 : t_out)) : t_out;
    store_pred((s.lane == 20) & t_ok, out + (size_t)t_clamped * BATCH + s.b, y);

    // Gate pre-activations: two independent 4-FMA chains per gate.
    float a0 = s.bias[0], a1 = s.bias[1], a2 = s.bias[2], a3 = s.bias[3];
    float p0, p1, p2, p3;
    a0 = fmaf(s.wih[0][0], iv0, a0); p0 = s.whh[0][0] * hv0;
    a1 = fmaf(s.wih[1][0], iv0, a1); p1 = s.whh[1][0] * hv0;
    a2 = fmaf(s.wih[2][0], iv0, a2); p2 = s.whh[2][0] * hv0;
    a3 = fmaf(s.wih[3][0], iv0, a3); p3 = s.whh[3][0] * hv0;

    a0 = fmaf(s.wih[0][1], iv1, a0); p0 = fmaf(s.whh[0][1], hv1, p0);
    a1 = fmaf(s.wih[1][1], iv1, a1); p1 = fmaf(s.whh[1][1], hv1, p1);
    a2 = fmaf(s.wih[2][1], iv1, a2); p2 = fmaf(s.whh[2][1], hv1, p2);
    a3 = fmaf(s.wih[3][1], iv1, a3); p3 = fmaf(s.whh[3][1], hv1, p3);

    a0 = fmaf(s.wih[0][2], iv2, a0); p0 = fmaf(s.whh[0][2], hv2, p0);
    a1 = fmaf(s.wih[1][2], iv2, a1); p1 = fmaf(s.whh[1][2], hv2, p1);
    a2 = fmaf(s.wih[2][2], iv2, a2); p2 = fmaf(s.whh[2][2], hv2, p2);
    a3 = fmaf(s.wih[3][2], iv2, a3); p3 = fmaf(s.whh[3][2], hv2, p3);

    a0 = fmaf(s.wih[0][3], iv3, a0); p0 = fmaf(s.whh[0][3], hv3, p0);
    a1 = fmaf(s.wih[1][3], iv3, a1); p1 = fmaf(s.whh[1][3], hv3, p1);
    a2 = fmaf(s.wih[2][3], iv3, a2); p2 = fmaf(s.whh[2][3], hv3, p2);
    a3 = fmaf(s.wih[3][3], iv3, a3); p3 = fmaf(s.whh[3][3], hv3, p3);

    // Gates: i,f,o pre-scaled by 0.5 (sigmoid-as-tanh fold); g unscaled.
    const float ti = tanh_ap(a0 + p0);      // tanh(0.5*gi)
    const float tf = tanh_ap(a1 + p1);      // tanh(0.5*gf)
    const float cc = tanh_ap(a2 + p2);      // tanh(gg)
    const float to = tanh_ap(a3 + p3);      // tanh(0.5*go)

    // c_new = sigm(f)*c + sigm(i)*cc = 0.5*[ (tf*c + c) + (ti*cc + cc) ]
    const float u  = fmaf(tf, s.c, s.c);
    const float v  = fmaf(ti, cc, cc);
    const float nc = fmaf(0.5f, u, 0.5f * v);
    // h' = 2*h = (to+1)*tanh(c)
    const float th = tanh_ap(nc);
    const float nh = fmaf(to, th, th);

    // Consume prefetched x, refill slot for tick k+UF.
    const float xv = xslot;
    xslot = __ldg(xptr);

    if (Guarded) {
        const int valid = ((unsigned)(k - s.l) < SEQ);
        const float nh2 = valid ? nh : s.h;
        const float nc2 = valid ? nc : s.c;
        s.h = s.isfeed ? xv : nh2;
        s.c = s.isfeed ? s.c : nc2;
    } else {
        s.h = s.isfeed ? xv : nh;
        s.c = nc;   // feeder's c is inert garbage; harmless
    }
}

__global__ __launch_bounds__(256) void lstm_reg_kernel(
    const float* __restrict__ x,      // [S, B, 4]
    const float* __restrict__ w_ih,   // [6, 16, 4]
    const float* __restrict__ w_hh,   // [6, 16, 4]
    const float* __restrict__ b_ih,   // [6, 16]
    const float* __restrict__ b_hh,   // [6, 16]
    const float* __restrict__ reg_w,  // [1, 4]
    const float* __restrict__ reg_b,  // [1]
    float* __restrict__ out)          // [S, B, 1]
{
    const int lane = threadIdx.x & 31;
    const int warp = threadIdx.x >> 5;
    if (lane >= 28) return;

    LaneState s;
    s.lane = lane;
    s.b = blockIdx.x * 8 + warp;
    s.l = lane >> 2;                     // 0..5 = LSTM layers, 6 = x feeder
    const int j = lane & 3;
    s.bh = s.l * 4;
    s.bi = (s.l == 0) ? 24 : (s.l - 1) * 4;
    s.isfeed = (s.l == 6);

#pragma unroll
    for (int g = 0; g < 4; ++g) {
#pragma unroll
        for (int i = 0; i < 4; ++i) { s.wih[g][i] = 0.f; s.whh[g][i] = 0.f; }
        s.bias[g] = 0.f;
    }
    if (s.l < 6) {
#pragma unroll
        for (int g = 0; g < 4; ++g) {
            const int row = s.l * 16 + g * 4 + j;       // gate order i,f,g,o
            const float gsc = (g == 2) ? 1.0f : 0.5f;   // sigmoid fold for i,f,o
            const float isc = (s.l == 0) ? 1.0f : 0.5f; // input is 2h for layers>0
#pragma unroll
            for (int i = 0; i < 4; ++i) {
                s.wih[g][i] = w_ih[row * 4 + i] * gsc * isc;
                s.whh[g][i] = w_hh[row * 4 + i] * gsc * 0.5f;  // own h is 2h
            }
            s.bias[g] = (b_ih[row] + b_hh[row]) * gsc;
        }
    }
    s.rw0 = reg_w[0] * 0.5f; s.rw1 = reg_w[1] * 0.5f;
    s.rw2 = reg_w[2] * 0.5f; s.rw3 = reg_w[3] * 0.5f;
    s.rb  = reg_b[0];

    s.h = 0.f; s.c = 0.f;
    const float* xq = x + (size_t)s.b * 4 + j;
    if (s.isfeed) s.h = xq[0];           // feeder starts with x[0] (NOT doubled;
                                         // layer-0 wih left unscaled by isc)

    // Prefetch ring: slot u holds x[tick+1] for tick ≡ u (mod UF).
    float xbuf[UF];
#pragma unroll
    for (int u = 0; u < UF; ++u) {
        const int idx = (u + 1 < SEQ) ? (u + 1) : (SEQ - 1);
        xbuf[u] = xq[(size_t)idx * BATCH * 4];
    }

    // ---- fill: ticks 0..7 (guarded) ----
#pragma unroll
    for (int u = 0; u < UF; ++u) {
        const int k = u;
        const int pidx = (k + 1 + UF < SEQ) ? (k + 1 + UF) : (SEQ - 1);
        tick<true>(k, s, xbuf[u], xq + (size_t)pidx * BATCH * 4, out);
    }

    // ---- main: ticks 8..2031, guard-free ----
#pragma unroll 1
    for (int kc = UF; kc < 2032; kc += UF) {
        const float* xb = xq + (size_t)(kc + 1 + UF) * BATCH * 4;
#pragma unroll
        for (int u = 0; u < UF; ++u)
            tick<false>(kc + u, s, xbuf[u], xb + (size_t)u * BATCH * 4, out);
    }

    // ---- drain: ticks 2032..2055 (guarded) ----
#pragma unroll 1
    for (int kc = 2032; kc < 2032 + 3 * UF; kc += UF) {
#pragma unroll
        for (int u = 0; u < UF; ++u) {
            const int k = kc + u;
            const int pidx = (k + 1 + UF < SEQ) ? (k + 1 + UF) : (SEQ - 1);
            tick<true>(k, s, xbuf[u], xq + (size_t)pidx * BATCH * 4, out);
        }
    }
}

extern "C" void kernel_launch(void* const* d_in, const int* in_sizes, int n_in,
                              void* d_out, int out_size) {
    const float* x     = (const float*)d_in[0];
    const float* w_ih  = (const float*)d_in[1];
    const float* w_hh  = (const float*)d_in[2];
    const float* b_ih  = (const float*)d_in[3];
    const float* b_hh  = (const float*)d_in[4];
    const float* reg_w = (const float*)d_in[5];
    const float* reg_b = (const float*)d_in[6];
    float* out = (float*)d_out;

    lstm_reg_kernel<<<128, 256>>>(x, w_ih, w_hh, b_ih, b_hh, reg_w, reg_b, out);
}